// round 6
// baseline (speedup 1.0000x reference)
#include <cuda_runtime.h>
#include <cuda_bf16.h>
#include <cstdint>
#include <cstddef>

// ---------------- problem constants ----------------
#define NB      65536

// padded k-strides (bf16 elems)
#define KP1 136                // k=128 tiles (rows 272B)
#define KPX 264                // k_l2 X tile k=256 (rows 528B)
#define KPW 136                // k_l2 W chunk k=128

// ---------------- smem layouts ----------------
#define SM1_VEC 0
#define SM1_XH  1024
#define SM1_XL  (SM1_XH + 34816)
#define SM1_WH  (SM1_XL + 34816)
#define SM1_WL  (SM1_WH + 34816)
#define SMEM_L1 (SM1_WL + 34816)     // 140288 B

#define SM2_XH  4096
#define SM2_XL  (SM2_XH + 67584)
#define SM2_WH  (SM2_XL + 67584)
#define SM2_WL  (SM2_WH + 34816)
#define SMEM_L2 (SM2_WL + 34816)     // 208896 B

// ---------------- device scratch ----------------
__device__ __align__(16) uint32_t g_x1h32[(size_t)NB * 128];  // x1 hi plane [B][256] bf16
__device__ __align__(16) uint32_t g_x1l32[(size_t)NB * 128];  // x1 lo plane
__device__ __align__(16) uint32_t g_w1h32[256 * 64];          // W1 hi [256][128] bf16
__device__ __align__(16) uint32_t g_w1l32[256 * 64];
__device__ __align__(16) uint32_t g_w2h32[256 * 128];         // W2 hi [256][256] bf16
__device__ __align__(16) uint32_t g_w2l32[256 * 128];
__device__ float g_wc[256];
__device__ float g_bc;

// ---------------- PTX helpers ----------------
__device__ __forceinline__ uint32_t smem_u32(const void* p) {
    uint32_t a;
    asm("{ .reg .u64 t; cvta.to.shared.u64 t, %1; cvt.u32.u64 %0, t; }" : "=r"(a) : "l"(p));
    return a;
}
__device__ __forceinline__ void cp16(uint32_t dst, const void* src) {
    asm volatile("cp.async.cg.shared.global [%0], [%1], 16;" :: "r"(dst), "l"(src));
}
#define CP_COMMIT() asm volatile("cp.async.commit_group;")
#define CP_WAIT0()  asm volatile("cp.async.wait_group 0;" ::: "memory")
#define CP_WAIT1()  asm volatile("cp.async.wait_group 1;" ::: "memory")

__device__ __forceinline__ void ldsm4(uint32_t* r, uint32_t addr) {
    asm volatile("ldmatrix.sync.aligned.m8n8.x4.shared.b16 {%0,%1,%2,%3}, [%4];"
        : "=r"(r[0]), "=r"(r[1]), "=r"(r[2]), "=r"(r[3]) : "r"(addr));
}
__device__ __forceinline__ void mma_bf16(float* c, const uint32_t* a, const uint32_t* b) {
    asm volatile(
        "mma.sync.aligned.m16n8k16.row.col.f32.bf16.bf16.f32 "
        "{%0,%1,%2,%3},{%4,%5,%6,%7},{%8,%9},{%0,%1,%2,%3};"
        : "+f"(c[0]), "+f"(c[1]), "+f"(c[2]), "+f"(c[3])
        : "r"(a[0]), "r"(a[1]), "r"(a[2]), "r"(a[3]), "r"(b[0]), "r"(b[1]));
}
__device__ __forceinline__ void split2(float v0, float v1, uint32_t& hi, uint32_t& lo) {
    __nv_bfloat16 h0 = __float2bfloat16(v0), h1 = __float2bfloat16(v1);
    __nv_bfloat16 l0 = __float2bfloat16(v0 - __bfloat162float(h0));
    __nv_bfloat16 l1 = __float2bfloat16(v1 - __bfloat162float(h1));
    hi = (uint32_t)*(uint16_t*)&h0 | ((uint32_t)*(uint16_t*)&h1 << 16);
    lo = (uint32_t)*(uint16_t*)&l0 | ((uint32_t)*(uint16_t*)&l1 << 16);
}

// one K=128 pass: warp tile 32x32, 8 ks-steps, 2 A-ldsm + 2 B-ldsm + 8 mma each
__device__ __forceinline__ void gemm_pass(float acc[2][4][4], uint32_t Ab, uint32_t Bb,
                                          int kpA, int kpW) {
    #pragma unroll
    for (int ks = 0; ks < 8; ks++) {
        uint32_t a[2][4], b[2][4];
        ldsm4(a[0], Ab + (ks * 16) * 2);
        ldsm4(a[1], Ab + (16 * kpA + ks * 16) * 2);
        ldsm4(b[0], Bb + (ks * 16) * 2);
        ldsm4(b[1], Bb + (16 * kpW + ks * 16) * 2);
        #pragma unroll
        for (int mi = 0; mi < 2; mi++) {
            mma_bf16(acc[mi][0], a[mi], &b[0][0]);
            mma_bf16(acc[mi][1], a[mi], &b[0][2]);
            mma_bf16(acc[mi][2], a[mi], &b[1][0]);
            mma_bf16(acc[mi][3], a[mi], &b[1][2]);
        }
    }
}

// ---------------- prep: weight splits + head collapse ----------------
__global__ void k_prep(const float* __restrict__ alphas,
                       const float* __restrict__ Wh, const float* __restrict__ bh,
                       const float* __restrict__ W1, const float* __restrict__ W2) {
    int bid = blockIdx.x, tid = threadIdx.x;
    if (bid == 0) {
        float s = 0.0f;
        for (int h = 0; h < 200; h++) s += alphas[h] * Wh[h * 256 + tid];
        g_wc[tid] = s;
        if (tid == 0) {
            float b = 0.0f;
            for (int h = 0; h < 200; h++) b += alphas[h] * bh[h];
            g_bc = b;
        }
    } else if (bid <= 64) {
        int i = (bid - 1) * 256 + tid;
        int row = i >> 6, kp = i & 63;
        split2(W1[row * 128 + kp * 2], W1[row * 128 + kp * 2 + 1], g_w1h32[i], g_w1l32[i]);
    } else {
        int j = (bid - 65) * 256 + tid;
        int row = j >> 7, kp = j & 127;
        split2(W2[row * 256 + kp * 2], W2[row * 256 + kp * 2 + 1], g_w2h32[j], g_w2l32[j]);
    }
}

// ---------------- layer 1: x1 = relu([state|action] @ W1^T + b1) -> hi/lo planes ----------------
__global__ __launch_bounds__(512, 1)
void k_l1(const float* __restrict__ state, const float* __restrict__ action,
          const float* __restrict__ b1)
{
    extern __shared__ char smem[];
    const uint32_t sb = smem_u32(smem);
    const int tid = threadIdx.x;
    const int nh  = blockIdx.x & 1;
    const int row0 = (blockIdx.x >> 1) * 128;

    // W1-half hi plane (group 1), lo plane (group 2) -- overlap with X split below
    for (int i = tid; i < 2048; i += 512) {
        int r = i >> 4, c = i & 15;
        cp16(sb + SM1_WH + r * 272 + c * 16, g_w1h32 + (size_t)(nh * 128 + r) * 64 + c * 4);
    }
    CP_COMMIT();
    for (int i = tid; i < 2048; i += 512) {
        int r = i >> 4, c = i & 15;
        cp16(sb + SM1_WL + r * 272 + c * 16, g_w1l32 + (size_t)(nh * 128 + r) * 64 + c * 4);
    }
    CP_COMMIT();

    float* b1s = (float*)(smem + SM1_VEC);
    if (tid < 128) b1s[tid] = b1[nh * 128 + tid];

    // X raw fp32 load + in-kernel split to hi/lo planes
    for (int i = tid; i < 128 * 32; i += 512) {
        int r = i >> 5, c4 = i & 31;
        float4 v = (c4 < 24)
            ? ((const float4*)(state + (size_t)(row0 + r) * 96))[c4]
            : ((const float4*)(action + (size_t)(row0 + r) * 32))[c4 - 24];
        uint32_t h01, l01, h23, l23;
        split2(v.x, v.y, h01, l01);
        split2(v.z, v.w, h23, l23);
        *(uint2*)(smem + SM1_XH + r * 272 + c4 * 8) = make_uint2(h01, h23);
        *(uint2*)(smem + SM1_XL + r * 272 + c4 * 8) = make_uint2(l01, l23);
    }

    CP_WAIT1();               // Wh plane ready (Wl may still be in flight)
    __syncthreads();

    const int wid = tid >> 5, lane = tid & 31;
    const int wm = (wid & 3) * 32, wn = (wid >> 2) * 32;
    const uint32_t aH = sb + SM1_XH + (((uint32_t)(wm + (lane & 15))) * KP1 + ((lane >> 4) * 8)) * 2;
    const uint32_t aL = sb + SM1_XL + (((uint32_t)(wm + (lane & 15))) * KP1 + ((lane >> 4) * 8)) * 2;
    const uint32_t bH = sb + SM1_WH + (((uint32_t)(wn + (lane & 7) + ((lane >> 4) * 8))) * KP1
                                        + (((lane >> 3) & 1) * 8)) * 2;
    const uint32_t bL = sb + SM1_WL + (((uint32_t)(wn + (lane & 7) + ((lane >> 4) * 8))) * KP1
                                        + (((lane >> 3) & 1) * 8)) * 2;

    float acc[2][4][4];
    #pragma unroll
    for (int i = 0; i < 2; i++)
        #pragma unroll
        for (int j = 0; j < 4; j++)
            #pragma unroll
            for (int c = 0; c < 4; c++) acc[i][j][c] = 0.0f;

    gemm_pass(acc, aH, bH, KP1, KP1);   // Ah * Wh
    gemm_pass(acc, aL, bH, KP1, KP1);   // Al * Wh  (Wl load hidden under these two)
    CP_WAIT0();
    __syncthreads();
    gemm_pass(acc, aH, bL, KP1, KP1);   // Ah * Wl

    // epilogue: bias + relu -> split hi/lo, store packed pairs
    const int g = lane >> 2, tg = lane & 3;
    #pragma unroll
    for (int mi = 0; mi < 2; mi++) {
        #pragma unroll
        for (int nj = 0; nj < 4; nj++) {
            int rA = row0 + wm + mi * 16 + g;
            int colL = wn + nj * 8 + tg * 2;
            float v0 = fmaxf(acc[mi][nj][0] + b1s[colL],     0.0f);
            float v1 = fmaxf(acc[mi][nj][1] + b1s[colL + 1], 0.0f);
            float v2 = fmaxf(acc[mi][nj][2] + b1s[colL],     0.0f);
            float v3 = fmaxf(acc[mi][nj][3] + b1s[colL + 1], 0.0f);
            uint32_t h01, l01, h23, l23;
            split2(v0, v1, h01, l01);
            split2(v2, v3, h23, l23);
            size_t ix = (size_t)rA * 128 + nh * 64 + (colL >> 1);
            g_x1h32[ix] = h01;            g_x1l32[ix] = l01;
            g_x1h32[ix + 8 * 128] = h23;  g_x1l32[ix + 8 * 128] = l23;
        }
    }
}

// ---------------- layer 2 + head fused, writes out directly ----------------
__global__ __launch_bounds__(512, 1)
void k_l2(const float* __restrict__ b2, float* __restrict__ out)
{
    extern __shared__ char smem[];
    const uint32_t sb = smem_u32(smem);
    const int tid = threadIdx.x;
    const int row0 = blockIdx.x * 128;

    float* b2s   = (float*)smem;            // [256]
    float* wcs   = b2s + 256;               // [256]
    float* stage = wcs + 256;               // [128]
    if (tid < 256) { b2s[tid] = b2[tid]; wcs[tid] = g_wc[tid]; }
    if (tid < 128) stage[tid] = 0.0f;

    // X planes (one commit group)
    for (int i = tid; i < 4096; i += 512) {
        int r = i >> 5, c = i & 31;
        cp16(sb + SM2_XH + r * 528 + c * 16, g_x1h32 + (size_t)(row0 + r) * 128 + c * 4);
        cp16(sb + SM2_XL + r * 528 + c * 16, g_x1l32 + (size_t)(row0 + r) * 128 + c * 4);
    }
    CP_COMMIT();
    // W chunk 0 (nh=0, kc=0): hi group, lo group
    for (int i = tid; i < 2048; i += 512) {
        int r = i >> 4, c = i & 15;
        cp16(sb + SM2_WH + r * 272 + c * 16, g_w2h32 + (size_t)r * 128 + c * 4);
    }
    CP_COMMIT();
    for (int i = tid; i < 2048; i += 512) {
        int r = i >> 4, c = i & 15;
        cp16(sb + SM2_WL + r * 272 + c * 16, g_w2l32 + (size_t)r * 128 + c * 4);
    }
    CP_COMMIT();

    const int wid = tid >> 5, lane = tid & 31;
    const int wm = (wid & 3) * 32, wn = (wid >> 2) * 32;
    const int g = lane >> 2, tg = lane & 3;
    const uint32_t aH = sb + SM2_XH + (((uint32_t)(wm + (lane & 15))) * KPX + ((lane >> 4) * 8)) * 2;
    const uint32_t aL = sb + SM2_XL + (((uint32_t)(wm + (lane & 15))) * KPX + ((lane >> 4) * 8)) * 2;
    const uint32_t bH = sb + SM2_WH + (((uint32_t)(wn + (lane & 7) + ((lane >> 4) * 8))) * KPW
                                        + (((lane >> 3) & 1) * 8)) * 2;
    const uint32_t bL = sb + SM2_WL + (((uint32_t)(wn + (lane & 7) + ((lane >> 4) * 8))) * KPW
                                        + (((lane >> 3) & 1) * 8)) * 2;

    float acc[2][4][4];
    float rs[2][2] = {{0.0f, 0.0f}, {0.0f, 0.0f}};
    #pragma unroll
    for (int i = 0; i < 2; i++)
        #pragma unroll
        for (int j = 0; j < 4; j++)
            #pragma unroll
            for (int c = 0; c < 4; c++) acc[i][j][c] = 0.0f;

    // chunks: (nh, kc) = (0,0),(0,1),(1,0),(1,1); W planes pipelined across chunks
    #pragma unroll 1
    for (int c = 0; c < 4; c++) {
        const int nh = c >> 1, kc = c & 1;
        const uint32_t ao = (uint32_t)kc * 256;   // kc*128 cols * 2B

        CP_WAIT1();                 // current Wh (and X on first iter) ready
        __syncthreads();
        gemm_pass(acc, aH + ao, bH, KPX, KPW);   // Ah * Wh
        gemm_pass(acc, aL + ao, bH, KPX, KPW);   // Al * Wh
        __syncthreads();            // all warps done with Wh buffer
        if (c < 3) {                // prefetch next chunk's Wh
            const int nnh = (c + 1) >> 1, nkc = (c + 1) & 1;
            for (int i = tid; i < 2048; i += 512) {
                int r = i >> 4, cc = i & 15;
                cp16(sb + SM2_WH + r * 272 + cc * 16,
                     g_w2h32 + (size_t)(nnh * 128 + r) * 128 + nkc * 64 + cc * 4);
            }
            CP_COMMIT();
            CP_WAIT1();             // current Wl ready (next Wh may pend)
        } else {
            CP_WAIT0();             // last chunk: drain everything
        }
        __syncthreads();
        gemm_pass(acc, aH + ao, bL, KPX, KPW);   // Ah * Wl
        __syncthreads();            // all warps done with Wl buffer
        if (c < 3) {                // prefetch next chunk's Wl
            const int nnh = (c + 1) >> 1, nkc = (c + 1) & 1;
            for (int i = tid; i < 2048; i += 512) {
                int r = i >> 4, cc = i & 15;
                cp16(sb + SM2_WL + r * 272 + cc * 16,
                     g_w2l32 + (size_t)(nnh * 128 + r) * 128 + nkc * 64 + cc * 4);
            }
            CP_COMMIT();
        }

        if (kc == 1) {   // finished K for this nh: fold bias+relu+head dot, reset acc
            #pragma unroll
            for (int mi = 0; mi < 2; mi++) {
                #pragma unroll
                for (int nj = 0; nj < 4; nj++) {
                    int n0 = nh * 128 + wn + nj * 8 + tg * 2;
                    float w0 = wcs[n0], w1 = wcs[n0 + 1];
                    float bb0 = b2s[n0], bb1 = b2s[n0 + 1];
                    rs[mi][0] += fmaxf(acc[mi][nj][0] + bb0, 0.0f) * w0
                               + fmaxf(acc[mi][nj][1] + bb1, 0.0f) * w1;
                    rs[mi][1] += fmaxf(acc[mi][nj][2] + bb0, 0.0f) * w0
                               + fmaxf(acc[mi][nj][3] + bb1, 0.0f) * w1;
                    acc[mi][nj][0] = 0.0f; acc[mi][nj][1] = 0.0f;
                    acc[mi][nj][2] = 0.0f; acc[mi][nj][3] = 0.0f;
                }
            }
        }
    }

    // reduce per-row scalars: quad shuffle + cross-warp smem atomics
    #pragma unroll
    for (int mi = 0; mi < 2; mi++) {
        #pragma unroll
        for (int rb = 0; rb < 2; rb++) {
            float s = rs[mi][rb];
            s += __shfl_xor_sync(0xFFFFFFFFu, s, 1);
            s += __shfl_xor_sync(0xFFFFFFFFu, s, 2);
            if (tg == 0) atomicAdd(&stage[wm + mi * 16 + g + rb * 8], s);
        }
    }
    __syncthreads();
    if (tid < 128) out[row0 + tid] = stage[tid] + g_bc;
}

// ---------------- launch ----------------
extern "C" void kernel_launch(void* const* d_in, const int* in_sizes, int n_in,
                              void* d_out, int out_size) {
    const float* state  = (const float*)d_in[0];
    const float* action = (const float*)d_in[1];
    const float* alphas = (const float*)d_in[2];
    const float* W1     = (const float*)d_in[3];
    const float* b1     = (const float*)d_in[4];
    const float* W2     = (const float*)d_in[5];
    const float* b2     = (const float*)d_in[6];
    const float* Wh     = (const float*)d_in[7];
    const float* bh     = (const float*)d_in[8];
    float* out = (float*)d_out;

    cudaFuncSetAttribute(k_l1, cudaFuncAttributeMaxDynamicSharedMemorySize, SMEM_L1);
    cudaFuncSetAttribute(k_l2, cudaFuncAttributeMaxDynamicSharedMemorySize, SMEM_L2);

    k_prep<<<193, 256>>>(alphas, Wh, bh, W1, W2);
    k_l1<<<1024, 512, SMEM_L1>>>(state, action, b1);
    k_l2<<<512, 512, SMEM_L2>>>(b2, out);
}